// round 1
// baseline (speedup 1.0000x reference)
#include <cuda_runtime.h>
#include <math.h>

#define KNN 32
#define VOCAB 32000
#define TOKENS 2048           // B*S = 4*512
#define NTHREADS 256
#define NV4 (VOCAB/4)         // 8000

__device__ __forceinline__ float warp_sum(float v) {
    #pragma unroll
    for (int o = 16; o > 0; o >>= 1) v += __shfl_xor_sync(0xffffffffu, v, o);
    return v;
}
__device__ __forceinline__ float warp_max(float v) {
    #pragma unroll
    for (int o = 16; o > 0; o >>= 1) v = fmaxf(v, __shfl_xor_sync(0xffffffffu, v, o));
    return v;
}

__global__ __launch_bounds__(NTHREADS) void robust_combiner_kernel(
    const int*   __restrict__ tgt_index,     // [T,32]
    const float* __restrict__ knn_dists,     // [T,32]
    const float* __restrict__ knn_key,       // [T,32]
    const float* __restrict__ net_probs,     // [T,32000]
    const float* __restrict__ net_sel,       // [T,32]
    const float* __restrict__ W_func, const float* __restrict__ b_func,   // [1,72],[1]
    const float* __restrict__ W1a,    const float* __restrict__ b1a,      // [4,2],[4]
    const float* __restrict__ W1b,    const float* __restrict__ b1b,      // [1,4],[1]
    const float* __restrict__ W2a,    const float* __restrict__ b2a,      // [32,64],[32]
    const float* __restrict__ W2b,    const float* __restrict__ b2b,      // [2,32],[2]
    float* __restrict__ out)                 // [T*32000] knn_prob then [T] knn_lambda
{
    const int t   = blockIdx.x;
    const int tid = threadIdx.x;

    __shared__ float s_top[NTHREADS * 8];
    __shared__ float s_W2a[32 * 64];
    __shared__ unsigned long long s_best[8];
    __shared__ float s_topv[8];
    __shared__ float s_d[KNN], s_cnt[KNN], s_p[KNN];
    __shared__ int   s_tgt[KNN];

    // stage W2a into shared (2048 floats, 8 per thread)
    #pragma unroll
    for (int j = 0; j < 8; j++) s_W2a[tid * 8 + j] = W2a[tid * 8 + j];
    if (tid < 8) s_best[tid] = 0ull;

    // ---------------- Phase 1: stream row, zero output row, local top-8 ----------------
    const float4* src = (const float4*)(net_probs + (size_t)t * VOCAB);
    float4*       dst = (float4*)(out + (size_t)t * VOCAB);
    const float4 z4 = make_float4(0.f, 0.f, 0.f, 0.f);

    // sorted descending top-8 in named registers (all probs > 0, so 0 sentinel ok)
    float t0 = 0.f, t1 = 0.f, t2 = 0.f, t3 = 0.f, t4 = 0.f, t5 = 0.f, t6 = 0.f, t7 = 0.f;

#define INS(v) do { float _v = (v);                                     \
    if (_v > t7) { t7 = _v;                                             \
        if (t7 > t6) { float _x = t6; t6 = t7; t7 = _x; }               \
        if (t6 > t5) { float _x = t5; t5 = t6; t6 = _x; }               \
        if (t5 > t4) { float _x = t4; t4 = t5; t5 = _x; }               \
        if (t4 > t3) { float _x = t3; t3 = t4; t4 = _x; }               \
        if (t3 > t2) { float _x = t2; t2 = t3; t3 = _x; }               \
        if (t2 > t1) { float _x = t1; t1 = t2; t2 = _x; }               \
        if (t1 > t0) { float _x = t0; t0 = t1; t1 = _x; }               \
    } } while (0)

    for (int i = tid; i < NV4; i += NTHREADS) {
        float4 v = src[i];
        dst[i] = z4;
        INS(v.x); INS(v.y); INS(v.z); INS(v.w);
    }
#undef INS

    s_top[tid * 8 + 0] = t0; s_top[tid * 8 + 1] = t1;
    s_top[tid * 8 + 2] = t2; s_top[tid * 8 + 3] = t3;
    s_top[tid * 8 + 4] = t4; s_top[tid * 8 + 5] = t5;
    s_top[tid * 8 + 6] = t6; s_top[tid * 8 + 7] = t7;
    __syncthreads();

    // ---------------- Phase 2: merge to global top-8 (8 extract-max rounds) ----------------
    {
        int p = 0;
        #pragma unroll
        for (int r = 0; r < 8; r++) {
            float cand = (p < 8) ? s_top[tid * 8 + p] : 0.0f;
            unsigned long long key =
                (((unsigned long long)__float_as_uint(cand)) << 32) | (unsigned)tid;
            atomicMax(&s_best[r], key);
            __syncthreads();
            unsigned long long w = s_best[r];
            if ((unsigned)(w & 0xffffffffull) == (unsigned)tid) p++;
            if (tid == 0) s_topv[r] = __uint_as_float((unsigned)(w >> 32));
        }
    }
    __syncthreads();

    // ---------------- Phase 3: scalar math on warp 0 ----------------
    if (tid < KNN) {
        const int k = tid;
        const int base = t * KNN;
        const int   tg = tgt_index[base + k];
        const float d  = knn_dists[base + k];
        const float lk = logf(knn_key[base + k]);
        const float ls = logf(net_sel[base + k]);
        s_tgt[k] = tg;
        s_d[k]   = d;
        __syncwarp();

        // distinct-nonzero-label prefix counts:
        // flag = (label != 0) && first occurrence; cnt = inclusive prefix sum
        int flag = (tg != 0) ? 1 : 0;
        for (int j = 0; j < k; j++)
            if (s_tgt[j] == tg) flag = 0;
        int c = flag;
        #pragma unroll
        for (int o = 1; o < 32; o <<= 1) {
            int v = __shfl_up_sync(0xffffffffu, c, o);
            if (k >= o) c += v;
        }
        s_cnt[k] = (float)c;
        __syncwarp();

        // noise_logit: Linear(2,4)-tanh-Linear(4,1)
        float noise = b1b[0];
        #pragma unroll
        for (int m = 0; m < 4; m++) {
            float h = tanhf(W1a[2 * m] * lk + W1a[2 * m + 1] * ls + b1a[m]);
            noise += W1b[m] * h;
        }

        // sim_lambda: dot([log(top8), log_key, log_sel], W_func) + b
        float part = lk * W_func[8 + k] + ls * W_func[40 + k];
        if (k < 8) part += logf(s_topv[k]) * W_func[k];
        float sim = warp_sum(part) + b_func[0];

        // lambda_logit: Linear(64,32)-tanh-Linear(32,2); lane k = hidden unit k
        float acc = b2a[k];
        #pragma unroll 8
        for (int j = 0; j < 32; j++)
            acc += s_W2a[k * 64 + j] * s_d[j] + s_W2a[k * 64 + 32 + j] * s_cnt[j];
        float h2 = tanhf(acc);
        float l0 = warp_sum(W2b[k]      * h2) + b2b[0];
        float l1 = warp_sum(W2b[32 + k] * h2) + b2b[1];

        // knn_lambda = softmax([l0, sim])[0] = sigmoid(l0 - sim)
        float lam   = 1.0f / (1.0f + expf(sim - l0));
        float tempe = 1.0f / (1.0f + expf(-l1));

        // probs = softmax(-d * tempe + noise) over K
        float logit = -d * tempe + noise;
        float mx = warp_max(logit);
        float e  = expf(logit - mx);
        float ssum = warp_sum(e);
        s_p[k] = e / ssum;
        __syncwarp();

        // ---------------- Phase 4: scatter (sequential, last-wins) + lambda ----------------
        if (k == 0) {
            float* row = out + (size_t)t * VOCAB;
            #pragma unroll
            for (int j = 0; j < KNN; j++) row[s_tgt[j]] = s_p[j];
            out[(size_t)TOKENS * VOCAB + t] = lam;
        }
    }
}

extern "C" void kernel_launch(void* const* d_in, const int* in_sizes, int n_in,
                              void* d_out, int out_size) {
    const int*   tgt_index = (const int*)  d_in[0];
    const float* knn_dists = (const float*)d_in[1];
    const float* knn_key   = (const float*)d_in[2];
    const float* net_probs = (const float*)d_in[3];
    const float* net_sel   = (const float*)d_in[4];
    const float* W_func    = (const float*)d_in[5];
    const float* b_func    = (const float*)d_in[6];
    const float* W1a       = (const float*)d_in[7];
    const float* b1a       = (const float*)d_in[8];
    const float* W1b       = (const float*)d_in[9];
    const float* b1b       = (const float*)d_in[10];
    const float* W2a       = (const float*)d_in[11];
    const float* b2a       = (const float*)d_in[12];
    const float* W2b       = (const float*)d_in[13];
    const float* b2b       = (const float*)d_in[14];
    float* out = (float*)d_out;

    robust_combiner_kernel<<<TOKENS, NTHREADS>>>(
        tgt_index, knn_dists, knn_key, net_probs, net_sel,
        W_func, b_func, W1a, b1a, W1b, b1b, W2a, b2a, W2b, b2b, out);
}

// round 2
// speedup vs baseline: 1.1006x; 1.1006x over previous
#include <cuda_runtime.h>
#include <math.h>

#define KNN 32
#define VOCAB 32000
#define TOKENS 2048           // B*S = 4*512
#define NTHREADS 256
#define NV4 (VOCAB/4)         // 8000 float4 per row

__device__ __forceinline__ float warp_sum(float v) {
    #pragma unroll
    for (int o = 16; o > 0; o >>= 1) v += __shfl_xor_sync(0xffffffffu, v, o);
    return v;
}
__device__ __forceinline__ float warp_max(float v) {
    #pragma unroll
    for (int o = 16; o > 0; o >>= 1) v = fmaxf(v, __shfl_xor_sync(0xffffffffu, v, o));
    return v;
}

__global__ __launch_bounds__(NTHREADS) void robust_combiner_kernel(
    const int*   __restrict__ tgt_index,     // [T,32]
    const float* __restrict__ knn_dists,     // [T,32]
    const float* __restrict__ knn_key,       // [T,32]
    const float* __restrict__ net_probs,     // [T,32000]
    const float* __restrict__ net_sel,       // [T,32]
    const float* __restrict__ W_func, const float* __restrict__ b_func,   // [1,72],[1]
    const float* __restrict__ W1a,    const float* __restrict__ b1a,      // [4,2],[4]
    const float* __restrict__ W1b,    const float* __restrict__ b1b,      // [1,4],[1]
    const float* __restrict__ W2a,    const float* __restrict__ b2a,      // [32,64],[32]
    const float* __restrict__ W2b,    const float* __restrict__ b2b,      // [2,32],[2]
    float* __restrict__ out)                 // [T*32000] knn_prob then [T] knn_lambda
{
    const int t   = blockIdx.x;
    const int tid = threadIdx.x;

    __shared__ float s_top[NTHREADS * 8];
    __shared__ float s_W2a[32 * 64];
    __shared__ unsigned long long s_best[8];
    __shared__ float s_topv[8];
    __shared__ float s_d[KNN], s_cnt[KNN], s_p[KNN];
    __shared__ int   s_tgt[KNN];

    // stage W2a into shared (2048 floats, 8 per thread)
    #pragma unroll
    for (int j = 0; j < 8; j++) s_W2a[tid * 8 + j] = W2a[tid * 8 + j];
    if (tid < 8) s_best[tid] = 0ull;

    // ---------------- Phase 1: stream row, zero output row, local top-8 ----------------
    const float4* __restrict__ src = (const float4*)(net_probs + (size_t)t * VOCAB);
    float4*       __restrict__ dst = (float4*)(out + (size_t)t * VOCAB);
    const float4 z4 = make_float4(0.f, 0.f, 0.f, 0.f);

    // sorted descending top-8 in named registers (all probs > 0, so 0 sentinel ok)
    float t0 = 0.f, t1 = 0.f, t2 = 0.f, t3 = 0.f, t4 = 0.f, t5 = 0.f, t6 = 0.f, t7 = 0.f;

#define INS(v) do { float _v = (v);                                     \
    if (_v > t7) { t7 = _v;                                             \
        if (t7 > t6) { float _x = t6; t6 = t7; t7 = _x; }               \
        if (t6 > t5) { float _x = t5; t5 = t6; t6 = _x; }               \
        if (t5 > t4) { float _x = t4; t4 = t5; t5 = _x; }               \
        if (t4 > t3) { float _x = t3; t3 = t4; t4 = _x; }               \
        if (t3 > t2) { float _x = t2; t2 = t3; t3 = _x; }               \
        if (t2 > t1) { float _x = t1; t1 = t2; t2 = _x; }               \
        if (t1 > t0) { float _x = t0; t0 = t1; t1 = _x; }               \
    } } while (0)

    // cheap filter: only enter insert path when max-of-4 beats current 8th best
#define PROC4(v) do {                                                   \
        float _m = fmaxf(fmaxf((v).x, (v).y), fmaxf((v).z, (v).w));    \
        if (_m > t7) { INS((v).x); INS((v).y); INS((v).z); INS((v).w); } \
    } while (0)

    // NV4 = 8000 = 256*31 + 64: main loop 31 full strides unrolled x2, then tail
    {
        int i = tid;
        #pragma unroll 1
        for (int it = 0; it < 15; it++) {
            float4 a = __ldcs(&src[i]);
            float4 b = __ldcs(&src[i + NTHREADS]);
            __stcs(&dst[i], z4);
            __stcs(&dst[i + NTHREADS], z4);
            PROC4(a);
            PROC4(b);
            i += 2 * NTHREADS;
        }
        // strides 30, 31(partial: 64 lanes)
        {
            float4 a = __ldcs(&src[i]);
            __stcs(&dst[i], z4);
            PROC4(a);
            i += NTHREADS;
            if (i < NV4) {
                float4 b = __ldcs(&src[i]);
                __stcs(&dst[i], z4);
                PROC4(b);
            }
        }
    }
#undef PROC4
#undef INS

    s_top[tid * 8 + 0] = t0; s_top[tid * 8 + 1] = t1;
    s_top[tid * 8 + 2] = t2; s_top[tid * 8 + 3] = t3;
    s_top[tid * 8 + 4] = t4; s_top[tid * 8 + 5] = t5;
    s_top[tid * 8 + 6] = t6; s_top[tid * 8 + 7] = t7;
    __syncthreads();

    // ---------------- Phase 2: merge to global top-8 (8 extract-max rounds) ----------------
    {
        int p = 0;
        #pragma unroll
        for (int r = 0; r < 8; r++) {
            float cand = (p < 8) ? s_top[tid * 8 + p] : 0.0f;
            unsigned long long key =
                (((unsigned long long)__float_as_uint(cand)) << 32) | (unsigned)tid;
            atomicMax(&s_best[r], key);
            __syncthreads();
            unsigned long long w = s_best[r];
            if ((unsigned)(w & 0xffffffffull) == (unsigned)tid) p++;
            if (tid == 0) s_topv[r] = __uint_as_float((unsigned)(w >> 32));
        }
    }
    __syncthreads();

    // ---------------- Phase 3: scalar math on warp 0 ----------------
    if (tid < KNN) {
        const int k = tid;
        const int base = t * KNN;
        const int   tg = tgt_index[base + k];
        const float d  = knn_dists[base + k];
        const float lk = logf(knn_key[base + k]);
        const float ls = logf(net_sel[base + k]);
        s_tgt[k] = tg;
        s_d[k]   = d;
        __syncwarp();

        // distinct-nonzero-label prefix counts:
        // flag = (label != 0) && first occurrence; cnt = inclusive prefix sum
        int flag = (tg != 0) ? 1 : 0;
        for (int j = 0; j < k; j++)
            if (s_tgt[j] == tg) flag = 0;
        int c = flag;
        #pragma unroll
        for (int o = 1; o < 32; o <<= 1) {
            int v = __shfl_up_sync(0xffffffffu, c, o);
            if (k >= o) c += v;
        }
        s_cnt[k] = (float)c;
        __syncwarp();

        // noise_logit: Linear(2,4)-tanh-Linear(4,1)
        float noise = b1b[0];
        #pragma unroll
        for (int m = 0; m < 4; m++) {
            float h = tanhf(W1a[2 * m] * lk + W1a[2 * m + 1] * ls + b1a[m]);
            noise += W1b[m] * h;
        }

        // sim_lambda: dot([log(top8), log_key, log_sel], W_func) + b
        float part = lk * W_func[8 + k] + ls * W_func[40 + k];
        if (k < 8) part += logf(s_topv[k]) * W_func[k];
        float sim = warp_sum(part) + b_func[0];

        // lambda_logit: Linear(64,32)-tanh-Linear(32,2); lane k = hidden unit k
        float acc = b2a[k];
        #pragma unroll 8
        for (int j = 0; j < 32; j++)
            acc += s_W2a[k * 64 + j] * s_d[j] + s_W2a[k * 64 + 32 + j] * s_cnt[j];
        float h2 = tanhf(acc);
        float l0 = warp_sum(W2b[k]      * h2) + b2b[0];
        float l1 = warp_sum(W2b[32 + k] * h2) + b2b[1];

        // knn_lambda = softmax([l0, sim])[0] = sigmoid(l0 - sim)
        float lam   = 1.0f / (1.0f + expf(sim - l0));
        float tempe = 1.0f / (1.0f + expf(-l1));

        // probs = softmax(-d * tempe + noise) over K
        float logit = -d * tempe + noise;
        float mx = warp_max(logit);
        float e  = expf(logit - mx);
        float ssum = warp_sum(e);
        s_p[k] = e / ssum;
        __syncwarp();

        // ---------------- Phase 4: scatter (sequential, last-wins) + lambda ----------------
        if (k == 0) {
            float* row = out + (size_t)t * VOCAB;
            #pragma unroll
            for (int j = 0; j < KNN; j++) row[s_tgt[j]] = s_p[j];
            out[(size_t)TOKENS * VOCAB + t] = lam;
        }
    }
}

extern "C" void kernel_launch(void* const* d_in, const int* in_sizes, int n_in,
                              void* d_out, int out_size) {
    const int*   tgt_index = (const int*)  d_in[0];
    const float* knn_dists = (const float*)d_in[1];
    const float* knn_key   = (const float*)d_in[2];
    const float* net_probs = (const float*)d_in[3];
    const float* net_sel   = (const float*)d_in[4];
    const float* W_func    = (const float*)d_in[5];
    const float* b_func    = (const float*)d_in[6];
    const float* W1a       = (const float*)d_in[7];
    const float* b1a       = (const float*)d_in[8];
    const float* W1b       = (const float*)d_in[9];
    const float* b1b       = (const float*)d_in[10];
    const float* W2a       = (const float*)d_in[11];
    const float* b2a       = (const float*)d_in[12];
    const float* W2b       = (const float*)d_in[13];
    const float* b2b       = (const float*)d_in[14];
    float* out = (float*)d_out;

    robust_combiner_kernel<<<TOKENS, NTHREADS>>>(
        tgt_index, knn_dists, knn_key, net_probs, net_sel,
        W_func, b_func, W1a, b1a, W1b, b1b, W2a, b2a, W2b, b2b, out);
}